// round 9
// baseline (speedup 1.0000x reference)
#include <cuda_runtime.h>
#include <cuda_bf16.h>
#include <math.h>
#include <stdint.h>

// ---------------------------------------------------------------------------
// LayerNormLSTM (2-layer bidirectional, reference has the aliasing bug that
// makes layer-1's input time-constant).  B=64, S=48, E=H=512, G=4H=2048.
// Round 8: tensor-core GEMMs (3-way bf16 split, 6 MMA terms, fp32-grade) and
// the whole recurrent scan fused into ONE persistent kernel per layer with
// grid-wide barriers (removes ~380 graph-node launches).
// ---------------------------------------------------------------------------

namespace {
constexpr int Bz = 64;
constexpr int Sz = 48;
constexpr int Ez = 512;
constexpr int Hz = 512;
constexpr int Gz = 2048;   // 4H
constexpr int KCH = 64;    // smem A-staging chunk (k elements)
constexpr int NCTA = 128;  // persistent scan grid (co-resident on 148 SMs)
constexpr float EPS = 1e-5f;
}

// ------------------------- static device scratch ---------------------------
__device__ __nv_bfloat16 g_xT[3][Sz * Bz][Ez];   // x transposed, 3 bf16 planes
__device__ float g_G0[2][Sz][Bz][Gz];            // layer0 LN(x @ W_ih^T) (50MB)
__device__ float g_G1[2][Bz][Gz];                // layer1 constant LN input
__device__ float g_Yp[2][2][Bz][Gz];             // [ksplit][dir] GEMM partials
__device__ float g_h[2][Bz][Hz];                 // hidden state fp32 (master)
__device__ float g_c[2][Bz][Hz];                 // cell state
__device__ __nv_bfloat16 g_hb[3][2][Bz][Hz];     // h bf16 planes
__device__ __nv_bfloat16 g_xc[3][Bz][2 * Hz];    // concat(hf,hb) planes

// Packed weights in mma B-fragment order (u32 = bf16 pair), 3 planes each:
// layout [nb(=n/8)][kc(=k/16)][reg(0..1)][lane(0..31)] per dir.
__device__ uint32_t g_wih0p[3][2][524288];
__device__ uint32_t g_whh0p[3][2][524288];
__device__ uint32_t g_whh1p[3][2][524288];
__device__ uint32_t g_wih1p[3][2][1048576];

// grid barrier state (generation is monotonic across launches/replays)
__device__ unsigned g_barcnt;
__device__ unsigned g_bargen;

// ------------------------- helpers -----------------------------------------
__device__ __forceinline__ uint32_t pk2(__nv_bfloat16 a, __nv_bfloat16 b) {
    __nv_bfloat162 t; t.x = a; t.y = b;
    return *reinterpret_cast<uint32_t*>(&t);
}

__device__ __forceinline__ void split3(float v, __nv_bfloat16& h,
                                       __nv_bfloat16& m, __nv_bfloat16& l) {
    h = __float2bfloat16(v);
    float r = v - __bfloat162float(h);
    m = __float2bfloat16(r);
    l = __float2bfloat16(r - __bfloat162float(m));
}

__device__ __forceinline__ void mma_bf16(float* d, const uint32_t* a,
                                         uint32_t b0, uint32_t b1) {
    asm volatile(
        "mma.sync.aligned.m16n8k16.row.col.f32.bf16.bf16.f32 "
        "{%0,%1,%2,%3}, {%4,%5,%6,%7}, {%8,%9}, {%0,%1,%2,%3};\n"
        : "+f"(d[0]), "+f"(d[1]), "+f"(d[2]), "+f"(d[3])
        : "r"(a[0]), "r"(a[1]), "r"(a[2]), "r"(a[3]), "r"(b0), "r"(b1));
}

// self-resetting grid barrier; bi-th barrier of this launch (bi >= 1)
__device__ __forceinline__ void gridbar(unsigned gen0, int bi) {
    __syncthreads();
    if (threadIdx.x == 0) {
        unsigned target = gen0 + (unsigned)bi;
        __threadfence();
        if (atomicAdd(&g_barcnt, 1u) == NCTA - 1) {
            atomicExch(&g_barcnt, 0u);        // reset BEFORE publishing release
            __threadfence();
            atomicExch(&g_bargen, target);
        } else {
            while ((int)(*(volatile unsigned*)&g_bargen - target) < 0) { }
        }
        __threadfence();
    }
    __syncthreads();
}

// ------------------------- small utility kernels ---------------------------
__global__ void zero_hc() {
    int i = blockIdx.x * blockDim.x + threadIdx.x;   // 65536 = 2*B*H
    (&g_h[0][0][0])[i] = 0.f;
    (&g_c[0][0][0])[i] = 0.f;
    __nv_bfloat16 z = __float2bfloat16(0.f);
    (&g_hb[0][0][0][0])[i] = z;
    (&g_hb[1][0][0][0])[i] = z;
    (&g_hb[2][0][0][0])[i] = z;
}

__global__ void transpose_x(const float* __restrict__ x) {
    int n = blockIdx.x;                   // n = s*B + b
    int s = n >> 6, b = n & 63;
    const float* src = x + ((size_t)b * Sz + s) * Ez;
    for (int i = threadIdx.x; i < Ez; i += blockDim.x) {
        __nv_bfloat16 h, m, l;
        split3(src[i], h, m, l);
        g_xT[0][n][i] = h; g_xT[1][n][i] = m; g_xT[2][n][i] = l;
    }
}

// Split + pack weights into mma fragment order. which: 0=wih0,1=whh0,2=whh1,3=wih1
__global__ void pack_w(const float* __restrict__ W, int which, int K) {
    int idx = blockIdx.x * blockDim.x + threadIdx.x;
    int k2n = K >> 1;
    int k2  = idx % k2n;
    int n   = (idx / k2n) & 2047;
    int dir = idx / (k2n * 2048);
    if (dir >= 2) return;

    uint32_t *p0, *p1, *p2;
    if (which == 0)      { p0 = &g_wih0p[0][dir][0]; p1 = &g_wih0p[1][dir][0]; p2 = &g_wih0p[2][dir][0]; }
    else if (which == 1) { p0 = &g_whh0p[0][dir][0]; p1 = &g_whh0p[1][dir][0]; p2 = &g_whh0p[2][dir][0]; }
    else if (which == 2) { p0 = &g_whh1p[0][dir][0]; p1 = &g_whh1p[1][dir][0]; p2 = &g_whh1p[2][dir][0]; }
    else                 { p0 = &g_wih1p[0][dir][0]; p1 = &g_wih1p[1][dir][0]; p2 = &g_wih1p[2][dir][0]; }

    int k = k2 * 2;
    const float* src = W + ((size_t)dir * 2048 + n) * K + k;
    __nv_bfloat16 h0, m0, l0, h1, m1, l1;
    split3(src[0], h0, m0, l0);
    split3(src[1], h1, m1, l1);

    int nb = n >> 3, grp = n & 7;
    int kc = k >> 4, kr = k & 15;
    int reg = kr >> 3;
    int tc  = (kr & 7) >> 1;
    int lane = grp * 4 + tc;
    int kpk = K >> 4;
    size_t pos = (((size_t)nb * kpk + kc) * 2 + reg) * 32 + lane;
    p0[pos] = pk2(h0, h1);
    p1[pos] = pk2(m0, m1);
    p2[pos] = pk2(l0, l1);
}

__global__ void xc_build() {
    int b = blockIdx.x, tid = threadIdx.x;
#pragma unroll
    for (int r = 0; r < 2; r++) {
        int j = tid + r * 256;
#pragma unroll
        for (int p = 0; p < 3; p++) {
            g_xc[p][b][j]       = g_hb[p][0][b][j];
            g_xc[p][b][512 + j] = g_hb[p][1][b][j];
        }
    }
}

__global__ void out_build(float* __restrict__ out) {
    int b = blockIdx.x, tid = threadIdx.x;
#pragma unroll
    for (int r = 0; r < 2; r++) {
        int j = tid + r * 256;
        out[(size_t)b * 1024 + j]       = g_h[0][b][j];
        out[(size_t)b * 1024 + 512 + j] = g_h[1][b][j];
    }
}

// ------------------------- block LN statistics -----------------------------
__device__ __forceinline__ float2 ln_stats(float s, float q, float n, float* sm) {
    __syncthreads();
#pragma unroll
    for (int o = 16; o; o >>= 1) {
        s += __shfl_xor_sync(0xffffffffu, s, o);
        q += __shfl_xor_sync(0xffffffffu, q, o);
    }
    int tid = threadIdx.x;
    if ((tid & 31) == 0) { sm[tid >> 5] = s; sm[(tid >> 5) + 8] = q; }
    __syncthreads();
    if (tid == 0) {
        float ts = 0.f, tq = 0.f;
#pragma unroll
        for (int w = 0; w < 8; w++) { ts += sm[w]; tq += sm[w + 8]; }
        float mu = ts / n;
        float var = tq / n - mu * mu;
        sm[16] = mu;
        sm[17] = rsqrtf(var + EPS);
    }
    __syncthreads();
    return make_float2(sm[16], sm[17]);
}

// ------------------------- row LayerNorm (in place) ------------------------
__global__ void ln_rows(int mode, const float* __restrict__ gamma,
                        const float* __restrict__ beta) {
    __shared__ float sm[32];
    int rows = mode ? Bz : Sz * Bz;
    int dir = blockIdx.y;
    float* row = (mode ? &g_G1[0][0][0] : &g_G0[0][0][0][0]) +
                 ((size_t)dir * rows + blockIdx.x) * Gz;
    int tid = threadIdx.x;

    float4 a = ((const float4*)row)[tid];
    float4 b = ((const float4*)row)[tid + 256];
    float s = a.x + a.y + a.z + a.w + b.x + b.y + b.z + b.w;
    float q = a.x * a.x + a.y * a.y + a.z * a.z + a.w * a.w +
              b.x * b.x + b.y * b.y + b.z * b.z + b.w * b.w;
    float2 st = ln_stats(s, q, (float)Gz, sm);

    const float* gg = gamma + (size_t)dir * Gz;
    const float* gb = beta + (size_t)dir * Gz;
    float4 gv = ((const float4*)gg)[tid];
    float4 bv = ((const float4*)gb)[tid];
    float4 o;
    o.x = (a.x - st.x) * st.y * gv.x + bv.x;
    o.y = (a.y - st.x) * st.y * gv.y + bv.y;
    o.z = (a.z - st.x) * st.y * gv.z + bv.z;
    o.w = (a.w - st.x) * st.y * gv.w + bv.w;
    ((float4*)row)[tid] = o;

    gv = ((const float4*)gg)[tid + 256];
    bv = ((const float4*)gb)[tid + 256];
    o.x = (b.x - st.x) * st.y * gv.x + bv.x;
    o.y = (b.y - st.x) * st.y * gv.y + bv.y;
    o.z = (b.z - st.x) * st.y * gv.z + bv.z;
    o.w = (b.w - st.x) * st.y * gv.w + bv.w;
    ((float4*)row)[tid + 256] = o;
}

// ------------------------- 64x64 tensor-core GEMM core ---------------------
// C[64,64] = A[64,klen] * W[64rows,klen]^T with 3-way bf16 split (6 MMA terms).
// sAbase: caller-provided smem, 3 planes x 64 rows x 72 bf16 (27648 B).
__device__ __forceinline__ void gemm_core(
    __nv_bfloat16* sAbase,
    const __nv_bfloat16* __restrict__ A0, const __nv_bfloat16* __restrict__ A1,
    const __nv_bfloat16* __restrict__ A2, int lda,
    const uint32_t* __restrict__ W0, const uint32_t* __restrict__ W1,
    const uint32_t* __restrict__ W2,
    int nb0, int kpk, int kc0,
    float* __restrict__ C, int ldc, int klen)
{
    __nv_bfloat16* sP0 = sAbase;
    __nv_bfloat16* sP1 = sAbase + 64 * 72;
    __nv_bfloat16* sP2 = sAbase + 2 * 64 * 72;

    int t = threadIdx.x;
    int warp = t >> 5, lane = t & 31;
    int mrow = (warp & 3) << 4;          // 0,16,32,48
    int nbw  = nb0 + (warp >> 2) * 4;    // + nt below
    int grp = lane >> 2, tc = lane & 3;

    float acc[4][4];
#pragma unroll
    for (int i = 0; i < 4; i++)
#pragma unroll
        for (int j = 0; j < 4; j++) acc[i][j] = 0.f;

    const uint32_t* s0 = (const uint32_t*)sP0;
    const uint32_t* s1 = (const uint32_t*)sP1;
    const uint32_t* s2 = (const uint32_t*)sP2;
    int awBase = (mrow + grp) * 36 + tc;

    for (int k0 = 0; k0 < klen; k0 += KCH) {
        __syncthreads();
        // stage A chunk [64 x 64] per plane, 16B copies
#pragma unroll
        for (int it = 0; it < 2; it++) {
            int i = t + it * 256;                 // 0..511
            int r = i >> 3, off = (i & 7) * 8;
            *(uint4*)&sP0[r * 72 + off] = *(const uint4*)(A0 + (size_t)r * lda + k0 + off);
            *(uint4*)&sP1[r * 72 + off] = *(const uint4*)(A1 + (size_t)r * lda + k0 + off);
            *(uint4*)&sP2[r * 72 + off] = *(const uint4*)(A2 + (size_t)r * lda + k0 + off);
        }
        __syncthreads();
#pragma unroll
        for (int kk = 0; kk < KCH / 16; kk++) {
            int aw = awBase + kk * 8;
            uint32_t ah[4], am[4], al[4];
            ah[0] = s0[aw]; ah[1] = s0[aw + 288]; ah[2] = s0[aw + 4]; ah[3] = s0[aw + 292];
            am[0] = s1[aw]; am[1] = s1[aw + 288]; am[2] = s1[aw + 4]; am[3] = s1[aw + 292];
            al[0] = s2[aw]; al[1] = s2[aw + 288]; al[2] = s2[aw + 4]; al[3] = s2[aw + 292];
            int kc = kc0 + (k0 >> 4) + kk;
#pragma unroll
            for (int nt = 0; nt < 4; nt++) {
                size_t base = (((size_t)(nbw + nt) * kpk + kc) * 2) * 32;
                uint32_t bh0 = W0[base + lane], bh1 = W0[base + 32 + lane];
                uint32_t bm0 = W1[base + lane], bm1 = W1[base + 32 + lane];
                uint32_t bl0 = W2[base + lane], bl1 = W2[base + 32 + lane];
                mma_bf16(acc[nt], ah, bh0, bh1);   // h*h
                mma_bf16(acc[nt], ah, bm0, bm1);   // h*m
                mma_bf16(acc[nt], am, bh0, bh1);   // m*h
                mma_bf16(acc[nt], ah, bl0, bl1);   // h*l
                mma_bf16(acc[nt], al, bh0, bh1);   // l*h
                mma_bf16(acc[nt], am, bm0, bm1);   // m*m
            }
        }
    }
    int ncol = (warp >> 2) << 5;
#pragma unroll
    for (int nt = 0; nt < 4; nt++) {
        float* cp = C + (size_t)(mrow + grp) * ldc + ncol + nt * 8 + 2 * tc;
        *(float2*)cp = make_float2(acc[nt][0], acc[nt][1]);
        *(float2*)(cp + 8 * ldc) = make_float2(acc[nt][2], acc[nt][3]);
    }
}

// ------------------------- input projections -------------------------------
// mode 0: G0raw[dir] = xT @ w_ih0[dir]^T   (M=3072, K=512)
// mode 1: G1raw[dir] = xc @ w_ih1[dir]^T   (M=64,   K=1024)
__global__ void gemm_nt(int mode) {
    __shared__ __align__(16) __nv_bfloat16 sA[3 * 64 * 72];
    int m0 = blockIdx.x << 6;
    int n0 = blockIdx.y << 6;
    int dir = blockIdx.z;
    if (mode == 0) {
        gemm_core(sA, &g_xT[0][m0][0], &g_xT[1][m0][0], &g_xT[2][m0][0], Ez,
                  &g_wih0p[0][dir][0], &g_wih0p[1][dir][0], &g_wih0p[2][dir][0],
                  n0 >> 3, 32, 0,
                  &g_G0[dir][0][0][0] + (size_t)m0 * Gz + n0, Gz, Ez);
    } else {
        gemm_core(sA, &g_xc[0][0][0], &g_xc[1][0][0], &g_xc[2][0][0], 2 * Hz,
                  &g_wih1p[0][dir][0], &g_wih1p[1][dir][0], &g_wih1p[2][dir][0],
                  n0 >> 3, 64, 0,
                  &g_G1[dir][0][0] + n0, Gz, 2 * Hz);
    }
}

// ------------------------- fused persistent scan ---------------------------
// 128 CTAs x 256 threads, co-resident.  Per step:
//   phase A (GEMM): cta -> (ntile 0..31, ks 0..1, dir 0..1)
//   gridbar
//   phase B (cell): cta -> (b 0..63, dir 0..1)
//   gridbar
__global__ void __launch_bounds__(256, 1)
scan_layer(int layer,
           const float* __restrict__ lnhh_g, const float* __restrict__ lnhh_b,
           const float* __restrict__ lnho_g, const float* __restrict__ lnho_b) {
    __shared__ __align__(16) __nv_bfloat16 sA[3 * 64 * 72];
    __shared__ float smred[32];
    float* sy = reinterpret_cast<float*>(sA);   // cell-phase overlay (8 KB)

    int cta = blockIdx.x, tid = threadIdx.x;

    // --- GEMM-phase mapping ---
    int gn0 = (cta & 31) << 6;
    int gks = (cta >> 5) & 1;
    int gdir = cta >> 6;
    const uint32_t* W0 = layer ? &g_whh1p[0][gdir][0] : &g_whh0p[0][gdir][0];
    const uint32_t* W1 = layer ? &g_whh1p[1][gdir][0] : &g_whh0p[1][gdir][0];
    const uint32_t* W2 = layer ? &g_whh1p[2][gdir][0] : &g_whh0p[2][gdir][0];
    const __nv_bfloat16* A0 = &g_hb[0][gdir][0][0] + gks * 256;
    const __nv_bfloat16* A1 = &g_hb[1][gdir][0][0] + gks * 256;
    const __nv_bfloat16* A2 = &g_hb[2][gdir][0][0] + gks * 256;
    float* Cp = &g_Yp[gks][gdir][0][0] + gn0;

    // --- cell-phase mapping ---
    int cb = cta & 63, cdir = cta >> 6;
    const float* y0 = &g_Yp[0][cdir][cb][0];
    const float* y1 = &g_Yp[1][cdir][cb][0];
    float* cst = &g_c[cdir][cb][0];
    float* hst = &g_h[cdir][cb][0];
    __nv_bfloat16* hb0 = &g_hb[0][cdir][cb][0];
    __nv_bfloat16* hb1 = &g_hb[1][cdir][cb][0];
    __nv_bfloat16* hb2 = &g_hb[2][cdir][cb][0];
    const float* gg  = lnhh_g + (size_t)cdir * Gz;
    const float* gb  = lnhh_b + (size_t)cdir * Gz;
    const float* og_ = lnho_g + (size_t)cdir * Hz;
    const float* ob_ = lnho_b + (size_t)cdir * Hz;

    unsigned gen0 = *(volatile unsigned*)&g_bargen;  // stable pre-launch value
    int bi = 0;

    for (int t = 0; t < Sz; t++) {
        // ---------------- phase A: Yp = h @ Whh^T (tile) ----------------
        gemm_core(sA, A0, A1, A2, Hz, W0, W1, W2,
                  gn0 >> 3, 32, gks * 16, Cp, Gz, 256);
        gridbar(gen0, ++bi);

        // ---------------- phase B: cell update --------------------------
        const float* gih = (layer == 0)
            ? &g_G0[cdir][cdir ? (Sz - 1 - t) : t][cb][0]
            : &g_G1[cdir][cb][0];

        // prefetch gih + old c early (hide DRAM/L2 latency)
        float gihr[4][2], cold[2];
#pragma unroll
        for (int r = 0; r < 2; r++) {
            int hh = tid + r * 256;
            gihr[0][r] = gih[hh];
            gihr[1][r] = gih[512 + hh];
            gihr[2][r] = gih[1024 + hh];
            gihr[3][r] = gih[1536 + hh];
            cold[r] = cst[hh];
        }

        float s = 0.f, q = 0.f;
#pragma unroll
        for (int r = 0; r < 2; r++) {
            int i4 = tid + r * 256;
            float4 p  = ((const float4*)y0)[i4];
            float4 p1 = ((const float4*)y1)[i4];
            p.x += p1.x; p.y += p1.y; p.z += p1.z; p.w += p1.w;
            ((float4*)sy)[i4] = p;
            s += p.x + p.y + p.z + p.w;
            q += p.x * p.x + p.y * p.y + p.z * p.z + p.w * p.w;
        }
        float2 st = ln_stats(s, q, (float)Gz, smred);

        float o_[2], c_[2];
        float cs = 0.f, cq = 0.f;
#pragma unroll
        for (int r = 0; r < 2; r++) {
            int hh = tid + r * 256;
            float gi = gihr[0][r] + (sy[hh]        - st.x) * st.y * gg[hh]        + gb[hh];
            float gf = gihr[1][r] + (sy[512 + hh]  - st.x) * st.y * gg[512 + hh]  + gb[512 + hh];
            float go = gihr[2][r] + (sy[1024 + hh] - st.x) * st.y * gg[1024 + hh] + gb[1024 + hh];
            float gz = gihr[3][r] + (sy[1536 + hh] - st.x) * st.y * gg[1536 + hh] + gb[1536 + hh];

            float ig = 1.f / (1.f + expf(-gi));
            float fg = 1.f / (1.f + expf(-gf));
            float og = 1.f / (1.f + expf(-go));
            float zg = tanhf(gz);

            float c = fg * cold[r] + ig * zg;
            cst[hh] = c;
            o_[r] = og; c_[r] = c;
            cs += c; cq += c * c;
        }
        float2 st2 = ln_stats(cs, cq, (float)Hz, smred);

#pragma unroll
        for (int r = 0; r < 2; r++) {
            int hh = tid + r * 256;
            float cn = (c_[r] - st2.x) * st2.y * og_[hh] + ob_[hh];
            float hv = o_[r] * tanhf(cn);
            hst[hh] = hv;
            __nv_bfloat16 h, m, l;
            split3(hv, h, m, l);
            hb0[hh] = h; hb1[hh] = m; hb2[hh] = l;
        }
        gridbar(gen0, ++bi);
    }
}

// ---------------------------------------------------------------------------
extern "C" void kernel_launch(void* const* d_in, const int* in_sizes, int n_in,
                              void* d_out, int out_size) {
    const float* x        = (const float*)d_in[0];
    // d_in[1] = text_length (unused by reference forward)
    const float* w_ih0    = (const float*)d_in[2];
    const float* w_hh0    = (const float*)d_in[3];
    const float* ln_ih0_g = (const float*)d_in[4];
    const float* ln_ih0_b = (const float*)d_in[5];
    const float* ln_hh0_g = (const float*)d_in[6];
    const float* ln_hh0_b = (const float*)d_in[7];
    const float* ln_ho0_g = (const float*)d_in[8];
    const float* ln_ho0_b = (const float*)d_in[9];
    const float* w_ih1    = (const float*)d_in[10];
    const float* w_hh1    = (const float*)d_in[11];
    const float* ln_ih1_g = (const float*)d_in[12];
    const float* ln_ih1_b = (const float*)d_in[13];
    const float* ln_hh1_g = (const float*)d_in[14];
    const float* ln_hh1_b = (const float*)d_in[15];
    const float* ln_ho1_g = (const float*)d_in[16];
    const float* ln_ho1_b = (const float*)d_in[17];
    float* out = (float*)d_out;

    // init + conversions + layer-0 projection (parallel part)
    zero_hc<<<256, 256>>>();
    transpose_x<<<Sz * Bz, 128>>>(x);
    pack_w<<<4096, 256>>>(w_ih0, 0, 512);
    pack_w<<<4096, 256>>>(w_hh0, 1, 512);
    pack_w<<<4096, 256>>>(w_hh1, 2, 512);
    pack_w<<<8192, 256>>>(w_ih1, 3, 1024);
    gemm_nt<<<dim3(48, 32, 2), 256>>>(0);
    ln_rows<<<dim3(Sz * Bz, 2), 256>>>(0, ln_ih0_g, ln_ih0_b);

    // layer-0 scan: one persistent kernel
    scan_layer<<<NCTA, 256>>>(0, ln_hh0_g, ln_hh0_b, ln_ho0_g, ln_ho0_b);

    // layer-1 constant input (aliasing bug: same input every timestep)
    xc_build<<<Bz, 256>>>();
    gemm_nt<<<dim3(1, 32, 2), 256>>>(1);
    ln_rows<<<dim3(Bz, 2), 256>>>(1, ln_ih1_g, ln_ih1_b);
    zero_hc<<<256, 256>>>();

    // layer-1 scan
    scan_layer<<<NCTA, 256>>>(1, ln_hh1_g, ln_hh1_b, ln_ho1_g, ln_ho1_b);

    out_build<<<Bz, 256>>>(out);
}

// round 11
// speedup vs baseline: 1.7062x; 1.7062x over previous
#include <cuda_runtime.h>
#include <cuda_bf16.h>
#include <math.h>
#include <stdint.h>

// ---------------------------------------------------------------------------
// LayerNormLSTM (2-layer bidirectional, reference has the aliasing bug that
// makes layer-1's input time-constant).  B=64, S=48, E=H=512, G=4H=2048.
// Round 10: mma.sync bf16 split-3 (6 terms, fp32-grade) with BOTH operands
// staged in smem (bulk coalesced copies) — no more per-mma L2 fragment loads.
// ---------------------------------------------------------------------------

namespace {
constexpr int Bz = 64;
constexpr int Sz = 48;
constexpr int Ez = 512;
constexpr int Hz = 512;
constexpr int Gz = 2048;   // 4H
constexpr float EPS = 1e-5f;
// dyn smem: A 3 planes x 64 x 72 bf16 (27648B) + W packed 6144 u32 (24576B)
constexpr int GSM = 27648 + 24576;   // 52224
}

// ------------------------- static device scratch ---------------------------
__device__ __nv_bfloat16 g_xT[3][Sz * Bz][Ez];   // x transposed, 3 bf16 planes
__device__ float g_G0[2][Sz][Bz][Gz];            // layer0 LN(x @ W_ih^T)
__device__ float g_G1[2][Bz][Gz];                // layer1 constant LN input
__device__ float g_Yp[2][2][Bz][Gz];             // [ksplit][dir] GEMM partials
__device__ float g_h[2][Bz][Hz];                 // hidden state fp32 (master)
__device__ float g_c[2][Bz][Hz];                 // cell state
__device__ __nv_bfloat16 g_hb[3][2][Bz][Hz];     // h bf16 planes
__device__ __nv_bfloat16 g_xc[3][Bz][2 * Hz];    // concat(hf,hb) planes

// Packed weights in mma B-fragment order (u32 = bf16 pair), 3 planes each:
// per dir: [nb(=n/8)][kpk(=K/16)][reg(0..1)][lane(0..31)]
__device__ uint32_t g_wi0p[3][2][524288];    // K=512
__device__ uint32_t g_wh0p[3][2][524288];    // K=512
__device__ uint32_t g_wh1p[3][2][524288];    // K=512
__device__ uint32_t g_wi1p[3][2][1048576];   // K=1024

// ------------------------- helpers -----------------------------------------
__device__ __forceinline__ uint32_t pk2(__nv_bfloat16 a, __nv_bfloat16 b) {
    __nv_bfloat162 t; t.x = a; t.y = b;
    return *reinterpret_cast<uint32_t*>(&t);
}

__device__ __forceinline__ void split3(float v, __nv_bfloat16& h,
                                       __nv_bfloat16& m, __nv_bfloat16& l) {
    h = __float2bfloat16(v);
    float r = v - __bfloat162float(h);
    m = __float2bfloat16(r);
    l = __float2bfloat16(r - __bfloat162float(m));
}

__device__ __forceinline__ void mma_bf16(float* d, const uint32_t* a,
                                         uint32_t b0, uint32_t b1) {
    asm volatile(
        "mma.sync.aligned.m16n8k16.row.col.f32.bf16.bf16.f32 "
        "{%0,%1,%2,%3}, {%4,%5,%6,%7}, {%8,%9}, {%0,%1,%2,%3};\n"
        : "+f"(d[0]), "+f"(d[1]), "+f"(d[2]), "+f"(d[3])
        : "r"(a[0]), "r"(a[1]), "r"(a[2]), "r"(a[3]), "r"(b0), "r"(b1));
}

// ------------------------- small utility kernels ---------------------------
__global__ void zero_hc() {
    int i = blockIdx.x * blockDim.x + threadIdx.x;   // 65536 = 2*B*H
    (&g_h[0][0][0])[i] = 0.f;
    (&g_c[0][0][0])[i] = 0.f;
    __nv_bfloat16 z = __float2bfloat16(0.f);
    (&g_hb[0][0][0][0])[i] = z;
    (&g_hb[1][0][0][0])[i] = z;
    (&g_hb[2][0][0][0])[i] = z;
}

__global__ void transpose_x(const float* __restrict__ x) {
    int n = blockIdx.x;                   // n = s*B + b
    int s = n >> 6, b = n & 63;
    const float* src = x + ((size_t)b * Sz + s) * Ez;
    for (int i = threadIdx.x; i < Ez; i += blockDim.x) {
        __nv_bfloat16 h, m, l;
        split3(src[i], h, m, l);
        g_xT[0][n][i] = h; g_xT[1][n][i] = m; g_xT[2][n][i] = l;
    }
}

// Split + pack W (fp32 [2][2048][K]) into 3 planes of mma B-fragment layout.
// dst plane stride = 2 * perdir, dir stride = perdir = 2048*(K/2) u32.
__global__ void pack_w(const float* __restrict__ W, uint32_t* __restrict__ dst,
                       int K) {
    int idx = blockIdx.x * blockDim.x + threadIdx.x;
    int k2n = K >> 1;
    int k2  = idx % k2n;
    int n   = (idx / k2n) & 2047;
    int dir = idx / (k2n * 2048);
    if (dir >= 2) return;

    int k = k2 * 2;
    const float* src = W + ((size_t)dir * 2048 + n) * K + k;
    __nv_bfloat16 h0, m0, l0, h1, m1, l1;
    split3(src[0], h0, m0, l0);
    split3(src[1], h1, m1, l1);

    int nb = n >> 3, grp = n & 7;
    int kc = k >> 4, kr = k & 15;
    int reg = kr >> 3;
    int tc  = (kr & 7) >> 1;
    int lane = grp * 4 + tc;
    int kpk = K >> 4;
    size_t perdir = (size_t)2048 * (K >> 1);
    size_t pos = (size_t)dir * perdir +
                 ((((size_t)nb * kpk + kc) * 2 + reg) * 32 + lane);
    dst[pos]              = pk2(h0, h1);
    dst[2 * perdir + pos] = pk2(m0, m1);
    dst[4 * perdir + pos] = pk2(l0, l1);
}

__global__ void xc_build() {
    int b = blockIdx.x, tid = threadIdx.x;
#pragma unroll
    for (int r = 0; r < 2; r++) {
        int j = tid + r * 256;
#pragma unroll
        for (int p = 0; p < 3; p++) {
            g_xc[p][b][j]       = g_hb[p][0][b][j];
            g_xc[p][b][512 + j] = g_hb[p][1][b][j];
        }
    }
}

__global__ void out_build(float* __restrict__ out) {
    int b = blockIdx.x, tid = threadIdx.x;
#pragma unroll
    for (int r = 0; r < 2; r++) {
        int j = tid + r * 256;
        out[(size_t)b * 1024 + j]       = g_h[0][b][j];
        out[(size_t)b * 1024 + 512 + j] = g_h[1][b][j];
    }
}

// ------------------------- block LN statistics -----------------------------
__device__ __forceinline__ float2 ln_stats(float s, float q, float n, float* sm) {
    __syncthreads();
#pragma unroll
    for (int o = 16; o; o >>= 1) {
        s += __shfl_xor_sync(0xffffffffu, s, o);
        q += __shfl_xor_sync(0xffffffffu, q, o);
    }
    int tid = threadIdx.x;
    if ((tid & 31) == 0) { sm[tid >> 5] = s; sm[(tid >> 5) + 8] = q; }
    __syncthreads();
    if (tid == 0) {
        float ts = 0.f, tq = 0.f;
#pragma unroll
        for (int w = 0; w < 8; w++) { ts += sm[w]; tq += sm[w + 8]; }
        float mu = ts / n;
        float var = tq / n - mu * mu;
        sm[16] = mu;
        sm[17] = rsqrtf(var + EPS);
    }
    __syncthreads();
    return make_float2(sm[16], sm[17]);
}

// ------------------------- row LayerNorm (in place) ------------------------
__global__ void ln_rows(int mode, const float* __restrict__ gamma,
                        const float* __restrict__ beta) {
    __shared__ float sm[32];
    int rows = mode ? Bz : Sz * Bz;
    int dir = blockIdx.y;
    float* row = (mode ? &g_G1[0][0][0] : &g_G0[0][0][0][0]) +
                 ((size_t)dir * rows + blockIdx.x) * Gz;
    int tid = threadIdx.x;

    float4 a = ((const float4*)row)[tid];
    float4 b = ((const float4*)row)[tid + 256];
    float s = a.x + a.y + a.z + a.w + b.x + b.y + b.z + b.w;
    float q = a.x * a.x + a.y * a.y + a.z * a.z + a.w * a.w +
              b.x * b.x + b.y * b.y + b.z * b.z + b.w * b.w;
    float2 st = ln_stats(s, q, (float)Gz, sm);

    const float* gg = gamma + (size_t)dir * Gz;
    const float* gb = beta + (size_t)dir * Gz;
    float4 gv = ((const float4*)gg)[tid];
    float4 bv = ((const float4*)gb)[tid];
    float4 o;
    o.x = (a.x - st.x) * st.y * gv.x + bv.x;
    o.y = (a.y - st.x) * st.y * gv.y + bv.y;
    o.z = (a.z - st.x) * st.y * gv.z + bv.z;
    o.w = (a.w - st.x) * st.y * gv.w + bv.w;
    ((float4*)row)[tid] = o;

    gv = ((const float4*)gg)[tid + 256];
    bv = ((const float4*)gb)[tid + 256];
    o.x = (b.x - st.x) * st.y * gv.x + bv.x;
    o.y = (b.y - st.x) * st.y * gv.y + bv.y;
    o.z = (b.z - st.x) * st.y * gv.z + bv.z;
    o.w = (b.w - st.x) * st.y * gv.w + bv.w;
    ((float4*)row)[tid + 256] = o;
}

// ------------------------- GEMM kernel (HMMA, smem-staged) ------------------
// C[64,64] tile of A[64,klen] * W[n-rows,klen]^T, 3-way split (6 terms).
// Per chunk (64 k): A planes -> smem (stride 36 u32, conflict-free), packed W
// fragments -> smem (bulk contiguous copy). Inner loop: LDS + mma only.
// mode 0: proj0  grid(32, 48, 2)  A=g_xT  klen=512  C=g_G0
// mode 1: proj1  grid(32, 1, 2)   A=g_xc  klen=1024 C=g_G1
// mode 2: scan0  grid(32, 2, 2)   A=g_hb  klen=256  C=g_Yp  (by = split-K)
// mode 3: scan1  same as 2 with whh1
__global__ void __launch_bounds__(256) mma_gemm(int mode) {
    extern __shared__ __align__(16) char dyn[];
    __nv_bfloat16* sA = (__nv_bfloat16*)dyn;            // 3 x 64 x 72
    uint32_t* sW = (uint32_t*)(dyn + 27648);            // 3 x 8nb x 4kc x 64
    uint4* sW4 = (uint4*)sW;

    int tid = threadIdx.x;
    int warp = tid >> 5, lane = tid & 31;
    int n0 = blockIdx.x << 6;
    int by = blockIdx.y;
    int dir = blockIdx.z;

    const __nv_bfloat16* Ap[3];
    const uint32_t* Wp[3];
    float* Cb;
    int lda, nch, kpk, kc0base;

    if (mode == 0) {
        lda = Ez; nch = 8; kpk = 32; kc0base = 0;
#pragma unroll
        for (int p = 0; p < 3; p++) {
            Ap[p] = &g_xT[p][by << 6][0];
            Wp[p] = &g_wi0p[p][dir][0];
        }
        Cb = &g_G0[dir][0][0][0] + ((size_t)(by << 6)) * Gz + n0;
    } else if (mode == 1) {
        lda = 2 * Hz; nch = 16; kpk = 64; kc0base = 0;
#pragma unroll
        for (int p = 0; p < 3; p++) {
            Ap[p] = &g_xc[p][0][0];
            Wp[p] = &g_wi1p[p][dir][0];
        }
        Cb = &g_G1[dir][0][0] + n0;
    } else {
        lda = Hz; nch = 4; kpk = 32; kc0base = by << 4;   // by*256 k offset
#pragma unroll
        for (int p = 0; p < 3; p++) {
            Ap[p] = &g_hb[p][dir][0][0] + by * 256;
            Wp[p] = (mode == 2) ? &g_wh0p[p][dir][0] : &g_wh1p[p][dir][0];
        }
        Cb = &g_Yp[by][dir][0][0] + n0;
    }
    int nb0 = n0 >> 3;

    int mrow = (warp & 3) << 4;          // 0,16,32,48
    int nhalf = warp >> 2;               // 0,1
    int grp = lane >> 2, tc = lane & 3;
    int awBase = (mrow + grp) * 36 + tc;

    float acc[4][4];
#pragma unroll
    for (int i = 0; i < 4; i++)
#pragma unroll
        for (int j = 0; j < 4; j++) acc[i][j] = 0.f;

    const uint32_t* s0 = (const uint32_t*)sA;
    const uint32_t* s1 = s0 + 64 * 36;
    const uint32_t* s2 = s0 + 2 * 64 * 36;

    for (int ch = 0; ch < nch; ch++) {
        int k0 = ch * 64;                 // offset within Ap's k-window
        int kc0 = kc0base + ch * 4;       // global kc for W
        __syncthreads();
        // ---- stage A: 3 planes x 64 rows x 64 k (8 uint4 per row) ----
#pragma unroll
        for (int it = 0; it < 2; it++) {
            int i = tid + it * 256;       // 0..511
            int r = i >> 3, off = (i & 7) * 8;
            *(uint4*)&sA[(0 * 64 + r) * 72 + off] =
                *(const uint4*)(Ap[0] + (size_t)r * lda + k0 + off);
            *(uint4*)&sA[(1 * 64 + r) * 72 + off] =
                *(const uint4*)(Ap[1] + (size_t)r * lda + k0 + off);
            *(uint4*)&sA[(2 * 64 + r) * 72 + off] =
                *(const uint4*)(Ap[2] + (size_t)r * lda + k0 + off);
        }
        // ---- stage W: 3 planes x 8 nb x (4kc x 64 u32 contiguous) ----
#pragma unroll
        for (int j = 0; j < 6; j++) {
            int i = tid + j * 256;        // 0..1535 uint4
            int p = i >> 9;               // /512
            int rem = i & 511;
            int nb = rem >> 6;            // /64
            int q = rem & 63;
            sW4[(p * 8 + nb) * 64 + q] =
                *((const uint4*)Wp[p] + ((size_t)(nb0 + nb) * kpk + kc0) * 16 + q);
        }
        __syncthreads();

#pragma unroll
        for (int kk = 0; kk < 4; kk++) {
            int aw = awBase + kk * 8;
            uint32_t ah[4], am[4], al[4];
            ah[0] = s0[aw]; ah[1] = s0[aw + 8 * 36]; ah[2] = s0[aw + 4]; ah[3] = s0[aw + 8 * 36 + 4];
            am[0] = s1[aw]; am[1] = s1[aw + 8 * 36]; am[2] = s1[aw + 4]; am[3] = s1[aw + 8 * 36 + 4];
            al[0] = s2[aw]; al[1] = s2[aw + 8 * 36]; al[2] = s2[aw + 4]; al[3] = s2[aw + 8 * 36 + 4];
#pragma unroll
            for (int nt = 0; nt < 4; nt++) {
                int wix = ((( (nhalf << 2) + nt) * 3 * 0 + 0), 0); (void)wix;
                int base = (((0 * 8 + (nhalf << 2) + nt) * 4 + kk) << 6);
                // plane bases: p*8*4*64 = p*2048
                uint32_t bh0 = sW[base + lane],        bh1 = sW[base + 32 + lane];
                uint32_t bm0 = sW[2048 + base + lane], bm1 = sW[2048 + base + 32 + lane];
                uint32_t bl0 = sW[4096 + base + lane], bl1 = sW[4096 + base + 32 + lane];
                mma_bf16(acc[nt], ah, bh0, bh1);   // h*h
                mma_bf16(acc[nt], ah, bm0, bm1);   // h*m
                mma_bf16(acc[nt], am, bh0, bh1);   // m*h
                mma_bf16(acc[nt], ah, bl0, bl1);   // h*l
                mma_bf16(acc[nt], al, bh0, bh1);   // l*h
                mma_bf16(acc[nt], am, bm0, bm1);   // m*m
            }
        }
    }

    int ncol = nhalf << 5;
#pragma unroll
    for (int nt = 0; nt < 4; nt++) {
        float* cp = Cb + (size_t)(mrow + grp) * Gz + ncol + nt * 8 + 2 * tc;
        *(float2*)cp = make_float2(acc[nt][0], acc[nt][1]);
        *(float2*)(cp + 8 * Gz) = make_float2(acc[nt][2], acc[nt][3]);
    }
}

// ------------------------- recurrent cell update ---------------------------
__global__ void step_cell(int layer, int t,
                          const float* __restrict__ lnhh_g,
                          const float* __restrict__ lnhh_b,
                          const float* __restrict__ lnho_g,
                          const float* __restrict__ lnho_b) {
    __shared__ float sy[Gz];
    __shared__ float sm[32];
    int b = blockIdx.x, dir = blockIdx.y, tid = threadIdx.x;

    const float* gih;
    if (layer == 0) {
        int ts_ = dir ? (Sz - 1 - t) : t;
        gih = &g_G0[dir][ts_][b][0];
    } else {
        gih = &g_G1[dir][b][0];
    }

    const float* y0 = &g_Yp[0][dir][b][0];
    const float* y1 = &g_Yp[1][dir][b][0];
    float s = 0.f, q = 0.f;
#pragma unroll
    for (int r = 0; r < 2; r++) {
        int i4 = tid + r * 256;
        float4 p  = ((const float4*)y0)[i4];
        float4 p1 = ((const float4*)y1)[i4];
        p.x += p1.x; p.y += p1.y; p.z += p1.z; p.w += p1.w;
        ((float4*)sy)[i4] = p;
        s += p.x + p.y + p.z + p.w;
        q += p.x * p.x + p.y * p.y + p.z * p.z + p.w * p.w;
    }
    float2 st = ln_stats(s, q, (float)Gz, sm);

    const float* gg = lnhh_g + (size_t)dir * Gz;
    const float* gb = lnhh_b + (size_t)dir * Gz;

    float o_[2], c_[2];
    float cs = 0.f, cq = 0.f;
#pragma unroll
    for (int r = 0; r < 2; r++) {
        int hh = tid + r * 256;
        float gi = gih[hh]        + (sy[hh]        - st.x) * st.y * gg[hh]        + gb[hh];
        float gf = gih[512 + hh]  + (sy[512 + hh]  - st.x) * st.y * gg[512 + hh]  + gb[512 + hh];
        float go = gih[1024 + hh] + (sy[1024 + hh] - st.x) * st.y * gg[1024 + hh] + gb[1024 + hh];
        float gz = gih[1536 + hh] + (sy[1536 + hh] - st.x) * st.y * gg[1536 + hh] + gb[1536 + hh];

        float ig = 1.f / (1.f + expf(-gi));
        float fg = 1.f / (1.f + expf(-gf));
        float og = 1.f / (1.f + expf(-go));
        float zg = tanhf(gz);

        float c = fg * g_c[dir][b][hh] + ig * zg;
        g_c[dir][b][hh] = c;
        o_[r] = og; c_[r] = c;
        cs += c; cq += c * c;
    }
    float2 st2 = ln_stats(cs, cq, (float)Hz, sm);

    const float* og_ = lnho_g + (size_t)dir * Hz;
    const float* ob_ = lnho_b + (size_t)dir * Hz;
#pragma unroll
    for (int r = 0; r < 2; r++) {
        int hh = tid + r * 256;
        float cn = (c_[r] - st2.x) * st2.y * og_[hh] + ob_[hh];
        float hv = o_[r] * tanhf(cn);
        g_h[dir][b][hh] = hv;
        __nv_bfloat16 h, m, l;
        split3(hv, h, m, l);
        g_hb[0][dir][b][hh] = h;
        g_hb[1][dir][b][hh] = m;
        g_hb[2][dir][b][hh] = l;
    }
}

// ---------------------------------------------------------------------------
extern "C" void kernel_launch(void* const* d_in, const int* in_sizes, int n_in,
                              void* d_out, int out_size) {
    const float* x        = (const float*)d_in[0];
    // d_in[1] = text_length (unused by reference forward)
    const float* w_ih0    = (const float*)d_in[2];
    const float* w_hh0    = (const float*)d_in[3];
    const float* ln_ih0_g = (const float*)d_in[4];
    const float* ln_ih0_b = (const float*)d_in[5];
    const float* ln_hh0_g = (const float*)d_in[6];
    const float* ln_hh0_b = (const float*)d_in[7];
    const float* ln_ho0_g = (const float*)d_in[8];
    const float* ln_ho0_b = (const float*)d_in[9];
    const float* w_ih1    = (const float*)d_in[10];
    const float* w_hh1    = (const float*)d_in[11];
    const float* ln_ih1_g = (const float*)d_in[12];
    const float* ln_ih1_b = (const float*)d_in[13];
    const float* ln_hh1_g = (const float*)d_in[14];
    const float* ln_hh1_b = (const float*)d_in[15];
    const float* ln_ho1_g = (const float*)d_in[16];
    const float* ln_ho1_b = (const float*)d_in[17];
    float* out = (float*)d_out;

    (void)cudaFuncSetAttribute(mma_gemm,
        cudaFuncAttributeMaxDynamicSharedMemorySize, GSM);

    uint32_t *pwi0, *pwh0, *pwh1, *pwi1;
    (void)cudaGetSymbolAddress((void**)&pwi0, g_wi0p);
    (void)cudaGetSymbolAddress((void**)&pwh0, g_wh0p);
    (void)cudaGetSymbolAddress((void**)&pwh1, g_wh1p);
    (void)cudaGetSymbolAddress((void**)&pwi1, g_wi1p);

    // init + conversions + packing
    zero_hc<<<256, 256>>>();
    transpose_x<<<Sz * Bz, 128>>>(x);
    pack_w<<<4096, 256>>>(w_ih0, pwi0, 512);
    pack_w<<<4096, 256>>>(w_hh0, pwh0, 512);
    pack_w<<<4096, 256>>>(w_hh1, pwh1, 512);
    pack_w<<<8192, 256>>>(w_ih1, pwi1, 1024);

    // layer-0 input projection + LN
    mma_gemm<<<dim3(32, 48, 2), 256, GSM>>>(0);
    ln_rows<<<dim3(Sz * Bz, 2), 256>>>(0, ln_ih0_g, ln_ih0_b);

    // layer-0 scan
    for (int t = 0; t < Sz; t++) {
        mma_gemm<<<dim3(32, 2, 2), 256, GSM>>>(2);
        step_cell<<<dim3(Bz, 2), 256>>>(0, t, ln_hh0_g, ln_hh0_b,
                                        ln_ho0_g, ln_ho0_b);
    }

    // layer-1 constant input (aliasing bug: same input every timestep)
    xc_build<<<Bz, 256>>>();
    mma_gemm<<<dim3(32, 1, 2), 256, GSM>>>(1);
    ln_rows<<<dim3(Bz, 2), 256>>>(1, ln_ih1_g, ln_ih1_b);
    zero_hc<<<256, 256>>>();

    // layer-1 scan
    for (int t = 0; t < Sz; t++) {
        mma_gemm<<<dim3(32, 2, 2), 256, GSM>>>(3);
        step_cell<<<dim3(Bz, 2), 256>>>(1, t, ln_hh1_g, ln_hh1_b,
                                        ln_ho1_g, ln_ho1_b);
    }

    out_build<<<Bz, 256>>>(out);
}